// round 13
// baseline (speedup 1.0000x reference)
#include <cuda_runtime.h>
#include <cuda_fp16.h>

// Problem: B=8192, C = N*D = 2048, K = 1024
#define C_DIM 2048
#define K_DIM 1024
#define B_MAX 8192

#define QSCALE 23.0f
#define QINV2 (1.0f / (QSCALE * QSCALE))
#define SHIFT 1024.0f

// ---------------- device scratch ----------------
__device__ signed char g_zb[(size_t)B_MAX * C_DIM];   // 16 MB int8
__device__ signed char g_wb[(size_t)K_DIM * C_DIM];   // 2 MB int8
__device__ __half g_scores[(size_t)B_MAX * K_DIM];    // 16 MB: dot - whalf + SHIFT
__device__ float g_whalf[K_DIM];
__device__ float g_znorm[B_MAX];
__device__ int   g_ind[B_MAX];
__device__ float g_bestsc[B_MAX];
__device__ unsigned char g_flag[B_MAX];
__device__ float g_loss;

#define MAXC 33
__device__ int g_npairs;
__device__ int g_pairs[(size_t)B_MAX * 8];
__device__ unsigned long long g_best[B_MAX];

__device__ __forceinline__ unsigned pack_s8(float4 v) {
    int a = max(-127, min(127, __float2int_rn(v.x * QSCALE)));
    int b = max(-127, min(127, __float2int_rn(v.y * QSCALE)));
    int c = max(-127, min(127, __float2int_rn(v.z * QSCALE)));
    int d = max(-127, min(127, __float2int_rn(v.w * QSCALE)));
    return (unsigned)(a & 0xff) | ((unsigned)(b & 0xff) << 8)
         | ((unsigned)(c & 0xff) << 16) | ((unsigned)(d & 0xff) << 24);
}

// ---------------- fused prep: blocks [0,K) -> w rows; [K, K+B) -> z rows ----------------
__global__ __launch_bounds__(256) void prep_k(const float* __restrict__ z,
                                              const float* __restrict__ w,
                                              signed char* __restrict__ zb,
                                              signed char* __restrict__ wb)
{
    const int blk = blockIdx.x;
    const int t = threadIdx.x;
    const bool is_w = blk < K_DIM;
    const int row = is_w ? blk : blk - K_DIM;
    if (blk == 0 && t == 0) { g_loss = 0.0f; g_npairs = 0; }

    const float* src = is_w ? (w + (size_t)row * C_DIM) : (z + (size_t)row * C_DIM);
    signed char* dst = is_w ? (wb + (size_t)row * C_DIM) : (zb + (size_t)row * C_DIM);

    const float4* s4 = (const float4*)src;
    float4 a = s4[t * 2];
    float4 b = s4[t * 2 + 1];

    uint2 u;
    u.x = pack_s8(a);
    u.y = pack_s8(b);
    ((uint2*)dst)[t] = u;

    float s = a.x * a.x + a.y * a.y + a.z * a.z + a.w * a.w
            + b.x * b.x + b.y * b.y + b.z * b.z + b.w * b.w;
    for (int o = 16; o > 0; o >>= 1) s += __shfl_down_sync(0xFFFFFFFFu, s, o);
    __shared__ float red[8];
    if ((t & 31) == 0) red[t >> 5] = s;
    __syncthreads();
    if (t == 0) {
        float tot = 0.0f;
        for (int i = 0; i < 8; i++) tot += red[i];
        if (is_w) g_whalf[row] = 0.5f * tot;
        else      g_znorm[row] = tot;
    }
}

// ---------------- int8 mma.sync GEMM; epilogue stores fp16 (dot - whalf + SHIFT) ----------------
#define BM 128
#define BN 128
#define BKB 128
#define STAGES 3
#define A_ST (BM * BKB)
#define B_ST (BN * BKB)
#define GSMEM (STAGES * (A_ST + B_ST) + 1024)
#define NITER (C_DIM / BKB)   // 16

#define SWZ128(off) ((off) ^ (((off) >> 3) & 0x70))

__device__ __forceinline__ unsigned smem_u32(const void* p) {
    unsigned a;
    asm("{ .reg .u64 t; cvta.to.shared.u64 t, %1; cvt.u32.u64 %0, t; }" : "=r"(a) : "l"(p));
    return a;
}
__device__ __forceinline__ void cp16(unsigned s, const void* g) {
    asm volatile("cp.async.cg.shared.global [%0], [%1], 16;" :: "r"(s), "l"(g));
}
__device__ __forceinline__ void ldm4(unsigned* d, unsigned addr) {
    asm volatile("ldmatrix.sync.aligned.m8n8.x4.shared.b16 {%0,%1,%2,%3}, [%4];"
                 : "=r"(d[0]), "=r"(d[1]), "=r"(d[2]), "=r"(d[3]) : "r"(addr));
}
__device__ __forceinline__ void mma_s8(int* c, const unsigned* a, unsigned b0, unsigned b1) {
    asm volatile(
        "mma.sync.aligned.m16n8k32.row.col.s32.s8.s8.s32 "
        "{%0,%1,%2,%3}, {%4,%5,%6,%7}, {%8,%9}, {%0,%1,%2,%3};"
        : "+r"(c[0]), "+r"(c[1]), "+r"(c[2]), "+r"(c[3])
        : "r"(a[0]), "r"(a[1]), "r"(a[2]), "r"(a[3]), "r"(b0), "r"(b1));
}

__global__ __launch_bounds__(256, 2) void gemm_k(
    const signed char* __restrict__ zb,
    const signed char* __restrict__ wb,
    __half* __restrict__ scores)
{
    extern __shared__ char dsm[];
    unsigned base = (smem_u32(dsm) + 1023u) & ~1023u;
    const unsigned aB = base;
    const unsigned bB = base + STAGES * A_ST;

    const int tid = threadIdx.x;
    const int wid = tid >> 5;
    const int lane = tid & 31;
    const int wm = wid & 3;
    const int wn = wid >> 2;

    const signed char* zrow = zb + (size_t)(blockIdx.x * BM) * C_DIM;
    const signed char* wrow = wb + (size_t)(blockIdx.y * BN) * C_DIM;

    const int lr = tid >> 3;
    const int lc = (tid & 7) * 16;

    int acc[2][8][4];
#pragma unroll
    for (int i = 0; i < 2; i++)
#pragma unroll
        for (int j = 0; j < 8; j++)
#pragma unroll
            for (int q = 0; q < 4; q++) acc[i][j][q] = 0;

#pragma unroll
    for (int s = 0; s < STAGES - 1; s++) {
        int kb = s * BKB;
#pragma unroll
        for (int r = 0; r < 4; r++) {
            int row = r * 32 + lr;
            cp16(aB + s * A_ST + SWZ128((unsigned)(row * BKB + lc)),
                 zrow + (size_t)row * C_DIM + kb + lc);
            cp16(bB + s * B_ST + SWZ128((unsigned)(row * BKB + lc)),
                 wrow + (size_t)row * C_DIM + kb + lc);
        }
        asm volatile("cp.async.commit_group;");
    }

    for (int i = 0; i < NITER; i++) {
        asm volatile("cp.async.wait_group %0;" :: "n"(STAGES - 2));
        __syncthreads();

        if (i + STAGES - 1 < NITER) {
            int s = (i + STAGES - 1) % STAGES;
            int kb = (i + STAGES - 1) * BKB;
#pragma unroll
            for (int r = 0; r < 4; r++) {
                int row = r * 32 + lr;
                cp16(aB + s * A_ST + SWZ128((unsigned)(row * BKB + lc)),
                     zrow + (size_t)row * C_DIM + kb + lc);
                cp16(bB + s * B_ST + SWZ128((unsigned)(row * BKB + lc)),
                     wrow + (size_t)row * C_DIM + kb + lc);
            }
        }
        asm volatile("cp.async.commit_group;");

        const unsigned aS = aB + (i % STAGES) * A_ST;
        const unsigned bS = bB + (i % STAGES) * B_ST;
        const int lrow = lane & 15;
        const int lhalf = (lane >> 4) * 16;

#pragma unroll
        for (int kk = 0; kk < 4; kk++) {
            const int kbyte = kk * 32;
            unsigned af[2][4];
#pragma unroll
            for (int mt = 0; mt < 2; mt++) {
                int row = wm * 32 + mt * 16 + lrow;
                ldm4(af[mt], aS + SWZ128((unsigned)(row * BKB + kbyte + lhalf)));
            }
            unsigned bf[4][4];
#pragma unroll
            for (int nt2 = 0; nt2 < 4; nt2++) {
                int row = wn * 64 + nt2 * 16 + lrow;
                ldm4(bf[nt2], bS + SWZ128((unsigned)(row * BKB + kbyte + lhalf)));
            }
#pragma unroll
            for (int mt = 0; mt < 2; mt++)
#pragma unroll
                for (int nt = 0; nt < 8; nt++) {
                    const unsigned* bv = bf[nt >> 1];
                    unsigned b0 = (nt & 1) ? bv[1] : bv[0];
                    unsigned b1 = (nt & 1) ? bv[3] : bv[2];
                    mma_s8(acc[mt][nt], af[mt], b0, b1);
                }
        }
    }

    const int r0 = blockIdx.x * BM + wm * 32 + (lane >> 2);
    const int c0 = blockIdx.y * BN + wn * 64 + (lane & 3) * 2;
#pragma unroll
    for (int mt = 0; mt < 2; mt++) {
#pragma unroll
        for (int nt = 0; nt < 8; nt++) {
            const int c = c0 + nt * 8;
            float wh0 = g_whalf[c];
            float wh1 = g_whalf[c + 1];
            __half* p = scores + (size_t)(r0 + mt * 16) * K_DIM + c;
            *(__half2*)p = __floats2half2_rn(
                (float)acc[mt][nt][0] * QINV2 - wh0 + SHIFT,
                (float)acc[mt][nt][1] * QINV2 - wh1 + SHIFT);
            *(__half2*)(p + 8 * K_DIM) = __floats2half2_rn(
                (float)acc[mt][nt][2] * QINV2 - wh0 + SHIFT,
                (float)acc[mt][nt][3] * QINV2 - wh1 + SHIFT);
        }
    }
}

// ---------------- scan: index-free max + candidate collection ----------------
#define MARGIN 7.0f

__global__ __launch_bounds__(256) void scan_k()
{
    const int b = blockIdx.x;
    const int t = threadIdx.x;
    const int lane = t & 31;
    const int wp = t >> 5;

    __shared__ float s_wv[8];
    __shared__ float s_best;
    __shared__ int   s_besti;
    __shared__ int   s_cnt;
    __shared__ int   s_base;
    __shared__ int   s_cand[MAXC];

    uint2 raw = ((const uint2*)(g_scores + (size_t)b * K_DIM))[t];
    __half2 p0 = *(__half2*)&raw.x;
    __half2 p1 = *(__half2*)&raw.y;

    __half2 m2 = __hmax2(p0, p1);
    float2 mf = __half22float2(m2);
    float mv = fmaxf(mf.x, mf.y);
    for (int o = 16; o > 0; o >>= 1)
        mv = fmaxf(mv, __shfl_down_sync(0xFFFFFFFFu, mv, o));
    if (lane == 0) s_wv[wp] = mv;
    if (t == 0) { s_cnt = 0; s_besti = K_DIM; }
    __syncthreads();
    if (t == 0) {
        float gb = s_wv[0];
        for (int i2 = 1; i2 < 8; i2++) gb = fmaxf(gb, s_wv[i2]);
        s_best = gb;
    }
    __syncthreads();
    const float best = s_best;
    const float th = best - MARGIN;

    float2 a = __half22float2(p0);
    float2 c = __half22float2(p1);
    float v[4] = { a.x, a.y, c.x, c.y };
#pragma unroll
    for (int j = 0; j < 4; j++) {
        if (v[j] >= th) {
            int p = atomicAdd(&s_cnt, 1);
            if (p < MAXC) s_cand[p] = 4 * t + j;
            if (v[j] == best) atomicMin(&s_besti, 4 * t + j);
        }
    }
    __syncthreads();
    int cnt = s_cnt < MAXC ? s_cnt : MAXC;
    if (t == 0) {
        g_ind[b] = s_besti;
        g_bestsc[b] = best;
        if (cnt > 1) {
            g_flag[b] = 1;
            g_best[b] = 0ULL;
            s_base = atomicAdd(&g_npairs, cnt);
        } else {
            g_flag[b] = 0;
        }
    }
    __syncthreads();
    if (cnt > 1 && t < cnt)
        g_pairs[s_base + t] = (b << 10) | s_cand[t];
}

// ---------------- refine: one 128-thread block per pair, exact fp32 dot ----------------
__global__ __launch_bounds__(128) void refine_k(const float* __restrict__ z,
                                                const float* __restrict__ w)
{
    const int t = threadIdx.x;
    const int lane = t & 31;
    const int wp = t >> 5;
    const int npairs = g_npairs;

    __shared__ float s_red[4];

    for (int pi = blockIdx.x; pi < npairs; pi += gridDim.x) {
        const int pk = g_pairs[pi];
        const int b = pk >> 10;
        const int k = pk & 1023;

        const float4* zr4 = (const float4*)(z + (size_t)b * C_DIM);
        const float4* wr4 = (const float4*)(w + (size_t)k * C_DIM);

        // 8 independent loads per thread (4 z + 4 w), 512 floats per warp-sweep
        float4 zv[4], wv[4];
#pragma unroll
        for (int d = 0; d < 4; d++) {
            zv[d] = zr4[t + d * 128];
            wv[d] = wr4[t + d * 128];
        }
        float p = 0.0f;
#pragma unroll
        for (int d = 0; d < 4; d++)
            p += zv[d].x * wv[d].x + zv[d].y * wv[d].y
               + zv[d].z * wv[d].z + zv[d].w * wv[d].w;

        for (int o = 16; o > 0; o >>= 1) p += __shfl_down_sync(0xFFFFFFFFu, p, o);
        if (lane == 0) s_red[wp] = p;
        __syncthreads();
        if (t == 0) {
            float dot = s_red[0] + s_red[1] + s_red[2] + s_red[3];
            float score = dot - g_whalf[k];
            unsigned ub = __float_as_uint(score);
            ub = (ub & 0x80000000u) ? ~ub : (ub | 0x80000000u);
            unsigned long long packed = ((unsigned long long)ub << 32) | (unsigned)(~(unsigned)k);
            atomicMax(&g_best[b], packed);
        }
        __syncthreads();
    }
}

// ---------------- gather: out = w[ind]; loss rl = znorm - 2*score_true ----------------
__global__ __launch_bounds__(256) void gather_k(const float* __restrict__ w,
                                                float* __restrict__ out)
{
    const int b = blockIdx.x;
    const int t = threadIdx.x;

    __shared__ int s_ind;
    if (t == 0) {
        int ind;
        float score_true;
        if (g_flag[b]) {
            unsigned long long pb = g_best[b];
            ind = (int)(~(unsigned)(pb & 0xFFFFFFFFu));
            unsigned ub = (unsigned)(pb >> 32);
            score_true = (ub & 0x80000000u) ? __uint_as_float(ub ^ 0x80000000u)
                                            : __uint_as_float(~ub);
        } else {
            ind = g_ind[b];
            score_true = g_bestsc[b] - SHIFT;
        }
        s_ind = ind;
        atomicAdd(&g_loss, g_znorm[b] - 2.0f * score_true);
    }
    __syncthreads();
    const int ind = s_ind;

    const float4* wr = (const float4*)(w + (size_t)ind * C_DIM);
    float4* o4 = (float4*)(out + (size_t)b * C_DIM);
#pragma unroll
    for (int c = t; c < C_DIM / 4; c += 256) {
        float4 wv = __ldg(&wr[c]);
        asm volatile("st.global.cs.v4.f32 [%0], {%1,%2,%3,%4};"
            :: "l"(o4 + c), "f"(wv.x), "f"(wv.y), "f"(wv.z), "f"(wv.w));
    }
}

__global__ void fin_k(float* out, int loss_idx, float inv_n) {
    out[loss_idx] = 12.5f * g_loss * inv_n;   // KLD_SCALE*(1+COMMITMENT_COST)*mse
}

extern "C" void kernel_launch(void* const* d_in, const int* in_sizes, int n_in,
                              void* d_out, int out_size)
{
    const float* z = (const float*)d_in[0];
    const float* w = (const float*)d_in[1];
    float* out = (float*)d_out;
    const int B = in_sizes[0] / C_DIM;   // 8192

    void* p_zb; cudaGetSymbolAddress(&p_zb, g_zb);
    void* p_wb; cudaGetSymbolAddress(&p_wb, g_wb);
    void* p_sc; cudaGetSymbolAddress(&p_sc, g_scores);

    cudaFuncSetAttribute(gemm_k, cudaFuncAttributeMaxDynamicSharedMemorySize, GSMEM);

    prep_k<<<K_DIM + B, 256>>>(z, w, (signed char*)p_zb, (signed char*)p_wb);

    dim3 ggrid(B / BM, K_DIM / BN);
    gemm_k<<<ggrid, 256, GSMEM>>>((const signed char*)p_zb,
                                  (const signed char*)p_wb,
                                  (__half*)p_sc);

    scan_k<<<B, 256>>>();
    refine_k<<<8192, 128>>>(z, w);
    gather_k<<<B, 256>>>(w, out);
    fin_k<<<1, 1>>>(out, out_size - 1, 1.0f / ((float)B * (float)C_DIM));
}

// round 16
// speedup vs baseline: 1.0711x; 1.0711x over previous
#include <cuda_runtime.h>
#include <cuda_fp16.h>

// Problem: B=8192, C = N*D = 2048, K = 1024
#define C_DIM 2048
#define K_DIM 1024
#define B_MAX 8192

#define QSCALE 23.0f
#define QINV2 (1.0f / (QSCALE * QSCALE))
#define SHIFT 1024.0f

// ---------------- device scratch ----------------
__device__ signed char g_zb[(size_t)B_MAX * C_DIM];   // 16 MB int8
__device__ signed char g_wb[(size_t)K_DIM * C_DIM];   // 2 MB int8
__device__ __half g_scores[(size_t)B_MAX * K_DIM];    // 16 MB: dot - whalf + SHIFT
__device__ float g_whalf[K_DIM];
__device__ float g_znorm[B_MAX];
__device__ int   g_ind[B_MAX];
__device__ float g_loss;

#define MAXC 33

__device__ __forceinline__ unsigned pack_s8(float4 v) {
    int a = max(-127, min(127, __float2int_rn(v.x * QSCALE)));
    int b = max(-127, min(127, __float2int_rn(v.y * QSCALE)));
    int c = max(-127, min(127, __float2int_rn(v.z * QSCALE)));
    int d = max(-127, min(127, __float2int_rn(v.w * QSCALE)));
    return (unsigned)(a & 0xff) | ((unsigned)(b & 0xff) << 8)
         | ((unsigned)(c & 0xff) << 16) | ((unsigned)(d & 0xff) << 24);
}

// ---------------- fused prep: blocks [0,K) -> w rows; [K, K+B) -> z rows ----------------
__global__ __launch_bounds__(256) void prep_k(const float* __restrict__ z,
                                              const float* __restrict__ w,
                                              signed char* __restrict__ zb,
                                              signed char* __restrict__ wb)
{
    const int blk = blockIdx.x;
    const int t = threadIdx.x;
    const bool is_w = blk < K_DIM;
    const int row = is_w ? blk : blk - K_DIM;
    if (blk == 0 && t == 0) g_loss = 0.0f;

    const float* src = is_w ? (w + (size_t)row * C_DIM) : (z + (size_t)row * C_DIM);
    signed char* dst = is_w ? (wb + (size_t)row * C_DIM) : (zb + (size_t)row * C_DIM);

    const float4* s4 = (const float4*)src;
    float4 a = s4[t * 2];
    float4 b = s4[t * 2 + 1];

    uint2 u;
    u.x = pack_s8(a);
    u.y = pack_s8(b);
    ((uint2*)dst)[t] = u;

    float s = a.x * a.x + a.y * a.y + a.z * a.z + a.w * a.w
            + b.x * b.x + b.y * b.y + b.z * b.z + b.w * b.w;
    for (int o = 16; o > 0; o >>= 1) s += __shfl_down_sync(0xFFFFFFFFu, s, o);
    __shared__ float red[8];
    if ((t & 31) == 0) red[t >> 5] = s;
    __syncthreads();
    if (t == 0) {
        float tot = 0.0f;
        for (int i = 0; i < 8; i++) tot += red[i];
        if (is_w) g_whalf[row] = 0.5f * tot;
        else      g_znorm[row] = tot;
    }
}

// ---------------- int8 mma.sync GEMM; epilogue stores fp16 (dot - whalf + SHIFT) ----------------
#define BM 128
#define BN 128
#define BKB 128
#define STAGES 3
#define A_ST (BM * BKB)
#define B_ST (BN * BKB)
#define GSMEM (STAGES * (A_ST + B_ST) + 1024)
#define NITER (C_DIM / BKB)   // 16

#define SWZ128(off) ((off) ^ (((off) >> 3) & 0x70))

__device__ __forceinline__ unsigned smem_u32(const void* p) {
    unsigned a;
    asm("{ .reg .u64 t; cvta.to.shared.u64 t, %1; cvt.u32.u64 %0, t; }" : "=r"(a) : "l"(p));
    return a;
}
__device__ __forceinline__ void cp16(unsigned s, const void* g) {
    asm volatile("cp.async.cg.shared.global [%0], [%1], 16;" :: "r"(s), "l"(g));
}
__device__ __forceinline__ void ldm4(unsigned* d, unsigned addr) {
    asm volatile("ldmatrix.sync.aligned.m8n8.x4.shared.b16 {%0,%1,%2,%3}, [%4];"
                 : "=r"(d[0]), "=r"(d[1]), "=r"(d[2]), "=r"(d[3]) : "r"(addr));
}
__device__ __forceinline__ void mma_s8(int* c, const unsigned* a, unsigned b0, unsigned b1) {
    asm volatile(
        "mma.sync.aligned.m16n8k32.row.col.s32.s8.s8.s32 "
        "{%0,%1,%2,%3}, {%4,%5,%6,%7}, {%8,%9}, {%0,%1,%2,%3};"
        : "+r"(c[0]), "+r"(c[1]), "+r"(c[2]), "+r"(c[3])
        : "r"(a[0]), "r"(a[1]), "r"(a[2]), "r"(a[3]), "r"(b0), "r"(b1));
}

__global__ __launch_bounds__(256, 2) void gemm_k(
    const signed char* __restrict__ zb,
    const signed char* __restrict__ wb,
    __half* __restrict__ scores)
{
    extern __shared__ char dsm[];
    unsigned base = (smem_u32(dsm) + 1023u) & ~1023u;
    const unsigned aB = base;
    const unsigned bB = base + STAGES * A_ST;

    const int tid = threadIdx.x;
    const int wid = tid >> 5;
    const int lane = tid & 31;
    const int wm = wid & 3;
    const int wn = wid >> 2;

    const signed char* zrow = zb + (size_t)(blockIdx.x * BM) * C_DIM;
    const signed char* wrow = wb + (size_t)(blockIdx.y * BN) * C_DIM;

    const int lr = tid >> 3;
    const int lc = (tid & 7) * 16;

    int acc[2][8][4];
#pragma unroll
    for (int i = 0; i < 2; i++)
#pragma unroll
        for (int j = 0; j < 8; j++)
#pragma unroll
            for (int q = 0; q < 4; q++) acc[i][j][q] = 0;

#pragma unroll
    for (int s = 0; s < STAGES - 1; s++) {
        int kb = s * BKB;
#pragma unroll
        for (int r = 0; r < 4; r++) {
            int row = r * 32 + lr;
            cp16(aB + s * A_ST + SWZ128((unsigned)(row * BKB + lc)),
                 zrow + (size_t)row * C_DIM + kb + lc);
            cp16(bB + s * B_ST + SWZ128((unsigned)(row * BKB + lc)),
                 wrow + (size_t)row * C_DIM + kb + lc);
        }
        asm volatile("cp.async.commit_group;");
    }

    for (int i = 0; i < NITER; i++) {
        asm volatile("cp.async.wait_group %0;" :: "n"(STAGES - 2));
        __syncthreads();

        if (i + STAGES - 1 < NITER) {
            int s = (i + STAGES - 1) % STAGES;
            int kb = (i + STAGES - 1) * BKB;
#pragma unroll
            for (int r = 0; r < 4; r++) {
                int row = r * 32 + lr;
                cp16(aB + s * A_ST + SWZ128((unsigned)(row * BKB + lc)),
                     zrow + (size_t)row * C_DIM + kb + lc);
                cp16(bB + s * B_ST + SWZ128((unsigned)(row * BKB + lc)),
                     wrow + (size_t)row * C_DIM + kb + lc);
            }
        }
        asm volatile("cp.async.commit_group;");

        const unsigned aS = aB + (i % STAGES) * A_ST;
        const unsigned bS = bB + (i % STAGES) * B_ST;
        const int lrow = lane & 15;
        const int lhalf = (lane >> 4) * 16;

#pragma unroll
        for (int kk = 0; kk < 4; kk++) {
            const int kbyte = kk * 32;
            unsigned af[2][4];
#pragma unroll
            for (int mt = 0; mt < 2; mt++) {
                int row = wm * 32 + mt * 16 + lrow;
                ldm4(af[mt], aS + SWZ128((unsigned)(row * BKB + kbyte + lhalf)));
            }
            unsigned bf[4][4];
#pragma unroll
            for (int nt2 = 0; nt2 < 4; nt2++) {
                int row = wn * 64 + nt2 * 16 + lrow;
                ldm4(bf[nt2], bS + SWZ128((unsigned)(row * BKB + kbyte + lhalf)));
            }
#pragma unroll
            for (int mt = 0; mt < 2; mt++)
#pragma unroll
                for (int nt = 0; nt < 8; nt++) {
                    const unsigned* bv = bf[nt >> 1];
                    unsigned b0 = (nt & 1) ? bv[1] : bv[0];
                    unsigned b1 = (nt & 1) ? bv[3] : bv[2];
                    mma_s8(acc[mt][nt], af[mt], b0, b1);
                }
        }
    }

    const int r0 = blockIdx.x * BM + wm * 32 + (lane >> 2);
    const int c0 = blockIdx.y * BN + wn * 64 + (lane & 3) * 2;
#pragma unroll
    for (int mt = 0; mt < 2; mt++) {
#pragma unroll
        for (int nt = 0; nt < 8; nt++) {
            const int c = c0 + nt * 8;
            float wh0 = g_whalf[c];
            float wh1 = g_whalf[c + 1];
            __half* p = scores + (size_t)(r0 + mt * 16) * K_DIM + c;
            *(__half2*)p = __floats2half2_rn(
                (float)acc[mt][nt][0] * QINV2 - wh0 + SHIFT,
                (float)acc[mt][nt][1] * QINV2 - wh1 + SHIFT);
            *(__half2*)(p + 8 * K_DIM) = __floats2half2_rn(
                (float)acc[mt][nt][2] * QINV2 - wh0 + SHIFT,
                (float)acc[mt][nt][3] * QINV2 - wh1 + SHIFT);
        }
    }
}

// ---------------- fused scan + exact refine + loss ----------------
#define MARGIN 7.0f

__global__ __launch_bounds__(256) void scanref_k(const float* __restrict__ z,
                                                 const float* __restrict__ w)
{
    const int b = blockIdx.x;
    const int t = threadIdx.x;
    const int lane = t & 31;
    const int wp = t >> 5;

    __shared__ float s_wv[8];
    __shared__ float s_best;
    __shared__ int   s_cnt;
    __shared__ int   s_cand[MAXC];
    __shared__ float s_red[8];

    // ---- scan: 4 scores per thread, index-free block max ----
    uint2 raw = ((const uint2*)(g_scores + (size_t)b * K_DIM))[t];
    __half2 p0 = *(__half2*)&raw.x;
    __half2 p1 = *(__half2*)&raw.y;

    __half2 m2 = __hmax2(p0, p1);
    float2 mf = __half22float2(m2);
    float mv = fmaxf(mf.x, mf.y);
    for (int o = 16; o > 0; o >>= 1)
        mv = fmaxf(mv, __shfl_down_sync(0xFFFFFFFFu, mv, o));
    if (lane == 0) s_wv[wp] = mv;
    if (t == 0) s_cnt = 0;
    __syncthreads();
    if (t == 0) {
        float gb = s_wv[0];
        for (int i2 = 1; i2 < 8; i2++) gb = fmaxf(gb, s_wv[i2]);
        s_best = gb;
    }
    __syncthreads();
    const float best = s_best;
    const float th = best - MARGIN;

    // ---- threshold pass: collect ALL candidates (approx best included) ----
    float2 a = __half22float2(p0);
    float2 c = __half22float2(p1);
    float v[4] = { a.x, a.y, c.x, c.y };
#pragma unroll
    for (int j = 0; j < 4; j++) {
        if (v[j] >= th) {
            int p = atomicAdd(&s_cnt, 1);
            if (p < MAXC) s_cand[p] = 4 * t + j;
        }
    }
    __syncthreads();
    const int cnt = s_cnt < MAXC ? s_cnt : MAXC;

    if (cnt <= 1) {
        // unambiguous winner: the single candidate
        if (t == 0) {
            int ind = s_cand[0];
            g_ind[b] = ind;
            atomicAdd(&g_loss, g_znorm[b] - 2.0f * (best - SHIFT));
        }
        return;
    }

    // ---- exact fp32 refine, block-wide, candidates serial ----
    const float4* zr4 = (const float4*)(z + (size_t)b * C_DIM);
    float4 za = zr4[t * 2];
    float4 zc = zr4[t * 2 + 1];

    float ebv = -3.4e38f;   // meaningful on t==0 only
    int   ebi = 0;
    for (int ci = 0; ci < cnt; ci++) {
        const int k = s_cand[ci];
        const float4* wr4 = (const float4*)(w + (size_t)k * C_DIM);
        float4 wa = wr4[t * 2];
        float4 wc = wr4[t * 2 + 1];
        float p = za.x * wa.x + za.y * wa.y + za.z * wa.z + za.w * wa.w
                + zc.x * wc.x + zc.y * wc.y + zc.z * wc.z + zc.w * wc.w;
        for (int o = 16; o > 0; o >>= 1) p += __shfl_down_sync(0xFFFFFFFFu, p, o);
        if (lane == 0) s_red[wp] = p;
        __syncthreads();
        if (t == 0) {
            float dot = s_red[0] + s_red[1] + s_red[2] + s_red[3]
                      + s_red[4] + s_red[5] + s_red[6] + s_red[7];
            float sc = dot - g_whalf[k];
            if (sc > ebv || (sc == ebv && k < ebi)) { ebv = sc; ebi = k; }
        }
        __syncthreads();
    }
    if (t == 0) {
        g_ind[b] = ebi;
        atomicAdd(&g_loss, g_znorm[b] - 2.0f * ebv);
    }
}

// ---------------- gather: pure broadcast copy out = w[ind] ----------------
__global__ __launch_bounds__(256) void gather_k(const float* __restrict__ w,
                                                float* __restrict__ out)
{
    const int b = blockIdx.x;
    const int t = threadIdx.x;
    const int ind = g_ind[b];

    const float4* wr = (const float4*)(w + (size_t)ind * C_DIM);
    float4* o4 = (float4*)(out + (size_t)b * C_DIM);
#pragma unroll
    for (int c = t; c < C_DIM / 4; c += 256) {
        float4 wv = __ldg(&wr[c]);
        asm volatile("st.global.cs.v4.f32 [%0], {%1,%2,%3,%4};"
            :: "l"(o4 + c), "f"(wv.x), "f"(wv.y), "f"(wv.z), "f"(wv.w));
    }
}

__global__ void fin_k(float* out, int loss_idx, float inv_n) {
    out[loss_idx] = 12.5f * g_loss * inv_n;   // KLD_SCALE*(1+COMMITMENT_COST)*mse
}

extern "C" void kernel_launch(void* const* d_in, const int* in_sizes, int n_in,
                              void* d_out, int out_size)
{
    const float* z = (const float*)d_in[0];
    const float* w = (const float*)d_in[1];
    float* out = (float*)d_out;
    const int B = in_sizes[0] / C_DIM;   // 8192

    void* p_zb; cudaGetSymbolAddress(&p_zb, g_zb);
    void* p_wb; cudaGetSymbolAddress(&p_wb, g_wb);
    void* p_sc; cudaGetSymbolAddress(&p_sc, g_scores);

    cudaFuncSetAttribute(gemm_k, cudaFuncAttributeMaxDynamicSharedMemorySize, GSMEM);

    prep_k<<<K_DIM + B, 256>>>(z, w, (signed char*)p_zb, (signed char*)p_wb);

    dim3 ggrid(B / BM, K_DIM / BN);
    gemm_k<<<ggrid, 256, GSMEM>>>((const signed char*)p_zb,
                                  (const signed char*)p_wb,
                                  (__half*)p_sc);

    scanref_k<<<B, 256>>>(z, w);
    gather_k<<<B, 256>>>(w, out);
    fin_k<<<1, 1>>>(out, out_size - 1, 1.0f / ((float)B * (float)C_DIM));
}

// round 17
// speedup vs baseline: 1.1111x; 1.0373x over previous
#include <cuda_runtime.h>
#include <cuda_fp16.h>

// Problem: B=8192, C = N*D = 2048, K = 1024
#define C_DIM 2048
#define K_DIM 1024
#define B_MAX 8192

#define QSCALE 23.0f
#define QINV2 (1.0f / (QSCALE * QSCALE))
#define SHIFT 1024.0f

// ---------------- device scratch ----------------
__device__ signed char g_zb[(size_t)B_MAX * C_DIM];   // 16 MB int8
__device__ signed char g_wb[(size_t)K_DIM * C_DIM];   // 2 MB int8
__device__ __half g_scores[(size_t)B_MAX * K_DIM];    // 16 MB: dot - whalf + SHIFT
__device__ float g_whalf[K_DIM];
__device__ float g_znorm[B_MAX];
__device__ float g_loss;

#define MAXC 33

__device__ __forceinline__ unsigned pack_s8(float4 v) {
    int a = max(-127, min(127, __float2int_rn(v.x * QSCALE)));
    int b = max(-127, min(127, __float2int_rn(v.y * QSCALE)));
    int c = max(-127, min(127, __float2int_rn(v.z * QSCALE)));
    int d = max(-127, min(127, __float2int_rn(v.w * QSCALE)));
    return (unsigned)(a & 0xff) | ((unsigned)(b & 0xff) << 8)
         | ((unsigned)(c & 0xff) << 16) | ((unsigned)(d & 0xff) << 24);
}

// ---------------- fused prep: blocks [0,K) -> w rows; [K, K+B) -> z rows ----------------
__global__ __launch_bounds__(256) void prep_k(const float* __restrict__ z,
                                              const float* __restrict__ w,
                                              signed char* __restrict__ zb,
                                              signed char* __restrict__ wb)
{
    const int blk = blockIdx.x;
    const int t = threadIdx.x;
    const bool is_w = blk < K_DIM;
    const int row = is_w ? blk : blk - K_DIM;
    if (blk == 0 && t == 0) g_loss = 0.0f;

    const float* src = is_w ? (w + (size_t)row * C_DIM) : (z + (size_t)row * C_DIM);
    signed char* dst = is_w ? (wb + (size_t)row * C_DIM) : (zb + (size_t)row * C_DIM);

    const float4* s4 = (const float4*)src;
    float4 a = s4[t * 2];
    float4 b = s4[t * 2 + 1];

    uint2 u;
    u.x = pack_s8(a);
    u.y = pack_s8(b);
    ((uint2*)dst)[t] = u;

    float s = a.x * a.x + a.y * a.y + a.z * a.z + a.w * a.w
            + b.x * b.x + b.y * b.y + b.z * b.z + b.w * b.w;
    for (int o = 16; o > 0; o >>= 1) s += __shfl_down_sync(0xFFFFFFFFu, s, o);
    __shared__ float red[8];
    if ((t & 31) == 0) red[t >> 5] = s;
    __syncthreads();
    if (t == 0) {
        float tot = 0.0f;
        for (int i = 0; i < 8; i++) tot += red[i];
        if (is_w) g_whalf[row] = 0.5f * tot;
        else      g_znorm[row] = tot;
    }
}

// ---------------- int8 mma.sync GEMM; epilogue stores fp16 (dot - whalf + SHIFT) ----------------
#define BM 128
#define BN 128
#define BKB 128
#define STAGES 3
#define A_ST (BM * BKB)
#define B_ST (BN * BKB)
#define GSMEM (STAGES * (A_ST + B_ST) + 1024)
#define NITER (C_DIM / BKB)   // 16

#define SWZ128(off) ((off) ^ (((off) >> 3) & 0x70))

__device__ __forceinline__ unsigned smem_u32(const void* p) {
    unsigned a;
    asm("{ .reg .u64 t; cvta.to.shared.u64 t, %1; cvt.u32.u64 %0, t; }" : "=r"(a) : "l"(p));
    return a;
}
__device__ __forceinline__ void cp16(unsigned s, const void* g) {
    asm volatile("cp.async.cg.shared.global [%0], [%1], 16;" :: "r"(s), "l"(g));
}
__device__ __forceinline__ void ldm4(unsigned* d, unsigned addr) {
    asm volatile("ldmatrix.sync.aligned.m8n8.x4.shared.b16 {%0,%1,%2,%3}, [%4];"
                 : "=r"(d[0]), "=r"(d[1]), "=r"(d[2]), "=r"(d[3]) : "r"(addr));
}
__device__ __forceinline__ void mma_s8(int* c, const unsigned* a, unsigned b0, unsigned b1) {
    asm volatile(
        "mma.sync.aligned.m16n8k32.row.col.s32.s8.s8.s32 "
        "{%0,%1,%2,%3}, {%4,%5,%6,%7}, {%8,%9}, {%0,%1,%2,%3};"
        : "+r"(c[0]), "+r"(c[1]), "+r"(c[2]), "+r"(c[3])
        : "r"(a[0]), "r"(a[1]), "r"(a[2]), "r"(a[3]), "r"(b0), "r"(b1));
}

__global__ __launch_bounds__(256, 2) void gemm_k(
    const signed char* __restrict__ zb,
    const signed char* __restrict__ wb,
    __half* __restrict__ scores)
{
    extern __shared__ char dsm[];
    unsigned base = (smem_u32(dsm) + 1023u) & ~1023u;
    const unsigned aB = base;
    const unsigned bB = base + STAGES * A_ST;

    const int tid = threadIdx.x;
    const int wid = tid >> 5;
    const int lane = tid & 31;
    const int wm = wid & 3;
    const int wn = wid >> 2;

    const signed char* zrow = zb + (size_t)(blockIdx.x * BM) * C_DIM;
    const signed char* wrow = wb + (size_t)(blockIdx.y * BN) * C_DIM;

    const int lr = tid >> 3;
    const int lc = (tid & 7) * 16;

    int acc[2][8][4];
#pragma unroll
    for (int i = 0; i < 2; i++)
#pragma unroll
        for (int j = 0; j < 8; j++)
#pragma unroll
            for (int q = 0; q < 4; q++) acc[i][j][q] = 0;

#pragma unroll
    for (int s = 0; s < STAGES - 1; s++) {
        int kb = s * BKB;
#pragma unroll
        for (int r = 0; r < 4; r++) {
            int row = r * 32 + lr;
            cp16(aB + s * A_ST + SWZ128((unsigned)(row * BKB + lc)),
                 zrow + (size_t)row * C_DIM + kb + lc);
            cp16(bB + s * B_ST + SWZ128((unsigned)(row * BKB + lc)),
                 wrow + (size_t)row * C_DIM + kb + lc);
        }
        asm volatile("cp.async.commit_group;");
    }

    for (int i = 0; i < NITER; i++) {
        asm volatile("cp.async.wait_group %0;" :: "n"(STAGES - 2));
        __syncthreads();

        if (i + STAGES - 1 < NITER) {
            int s = (i + STAGES - 1) % STAGES;
            int kb = (i + STAGES - 1) * BKB;
#pragma unroll
            for (int r = 0; r < 4; r++) {
                int row = r * 32 + lr;
                cp16(aB + s * A_ST + SWZ128((unsigned)(row * BKB + lc)),
                     zrow + (size_t)row * C_DIM + kb + lc);
                cp16(bB + s * B_ST + SWZ128((unsigned)(row * BKB + lc)),
                     wrow + (size_t)row * C_DIM + kb + lc);
            }
        }
        asm volatile("cp.async.commit_group;");

        const unsigned aS = aB + (i % STAGES) * A_ST;
        const unsigned bS = bB + (i % STAGES) * B_ST;
        const int lrow = lane & 15;
        const int lhalf = (lane >> 4) * 16;

#pragma unroll
        for (int kk = 0; kk < 4; kk++) {
            const int kbyte = kk * 32;
            unsigned af[2][4];
#pragma unroll
            for (int mt = 0; mt < 2; mt++) {
                int row = wm * 32 + mt * 16 + lrow;
                ldm4(af[mt], aS + SWZ128((unsigned)(row * BKB + kbyte + lhalf)));
            }
            unsigned bf[4][4];
#pragma unroll
            for (int nt2 = 0; nt2 < 4; nt2++) {
                int row = wn * 64 + nt2 * 16 + lrow;
                ldm4(bf[nt2], bS + SWZ128((unsigned)(row * BKB + kbyte + lhalf)));
            }
#pragma unroll
            for (int mt = 0; mt < 2; mt++)
#pragma unroll
                for (int nt = 0; nt < 8; nt++) {
                    const unsigned* bv = bf[nt >> 1];
                    unsigned b0 = (nt & 1) ? bv[1] : bv[0];
                    unsigned b1 = (nt & 1) ? bv[3] : bv[2];
                    mma_s8(acc[mt][nt], af[mt], b0, b1);
                }
        }
    }

    const int r0 = blockIdx.x * BM + wm * 32 + (lane >> 2);
    const int c0 = blockIdx.y * BN + wn * 64 + (lane & 3) * 2;
#pragma unroll
    for (int mt = 0; mt < 2; mt++) {
#pragma unroll
        for (int nt = 0; nt < 8; nt++) {
            const int c = c0 + nt * 8;
            float wh0 = g_whalf[c];
            float wh1 = g_whalf[c + 1];
            __half* p = scores + (size_t)(r0 + mt * 16) * K_DIM + c;
            *(__half2*)p = __floats2half2_rn(
                (float)acc[mt][nt][0] * QINV2 - wh0 + SHIFT,
                (float)acc[mt][nt][1] * QINV2 - wh1 + SHIFT);
            *(__half2*)(p + 8 * K_DIM) = __floats2half2_rn(
                (float)acc[mt][nt][2] * QINV2 - wh0 + SHIFT,
                (float)acc[mt][nt][3] * QINV2 - wh1 + SHIFT);
        }
    }
}

// ---------------- fused scan + exact refine + loss + output gather ----------------
#define MARGIN 7.0f

__global__ __launch_bounds__(256) void scanref_k(const float* __restrict__ z,
                                                 const float* __restrict__ w,
                                                 float* __restrict__ out)
{
    const int b = blockIdx.x;
    const int t = threadIdx.x;
    const int lane = t & 31;
    const int wp = t >> 5;

    __shared__ float s_wv[8];
    __shared__ float s_best;
    __shared__ int   s_cnt;
    __shared__ int   s_cand[MAXC];
    __shared__ float s_red[8];
    __shared__ int   s_ind;

    // ---- scan: 4 scores per thread, index-free block max ----
    uint2 raw = ((const uint2*)(g_scores + (size_t)b * K_DIM))[t];
    __half2 p0 = *(__half2*)&raw.x;
    __half2 p1 = *(__half2*)&raw.y;

    __half2 m2 = __hmax2(p0, p1);
    float2 mf = __half22float2(m2);
    float mv = fmaxf(mf.x, mf.y);
    for (int o = 16; o > 0; o >>= 1)
        mv = fmaxf(mv, __shfl_down_sync(0xFFFFFFFFu, mv, o));
    if (lane == 0) s_wv[wp] = mv;
    if (t == 0) s_cnt = 0;
    __syncthreads();
    if (t == 0) {
        float gb = s_wv[0];
        for (int i2 = 1; i2 < 8; i2++) gb = fmaxf(gb, s_wv[i2]);
        s_best = gb;
    }
    __syncthreads();
    const float best = s_best;
    const float th = best - MARGIN;

    // ---- threshold pass: collect ALL candidates (approx best included) ----
    float2 a = __half22float2(p0);
    float2 c = __half22float2(p1);
    float v[4] = { a.x, a.y, c.x, c.y };
#pragma unroll
    for (int j = 0; j < 4; j++) {
        if (v[j] >= th) {
            int p = atomicAdd(&s_cnt, 1);
            if (p < MAXC) s_cand[p] = 4 * t + j;
        }
    }
    __syncthreads();
    const int cnt = s_cnt < MAXC ? s_cnt : MAXC;

    if (cnt <= 1) {
        // unambiguous winner
        if (t == 0) {
            s_ind = s_cand[0];
            atomicAdd(&g_loss, g_znorm[b] - 2.0f * (best - SHIFT));
        }
    } else {
        // ---- exact fp32 refine, block-wide, candidates serial ----
        const float4* zr4 = (const float4*)(z + (size_t)b * C_DIM);
        float4 za = zr4[t * 2];
        float4 zc = zr4[t * 2 + 1];

        float ebv = -3.4e38f;   // meaningful on t==0 only
        int   ebi = 0;
        for (int ci = 0; ci < cnt; ci++) {
            const int k = s_cand[ci];
            const float4* wr4 = (const float4*)(w + (size_t)k * C_DIM);
            float4 wa = wr4[t * 2];
            float4 wc = wr4[t * 2 + 1];
            float p = za.x * wa.x + za.y * wa.y + za.z * wa.z + za.w * wa.w
                    + zc.x * wc.x + zc.y * wc.y + zc.z * wc.z + zc.w * wc.w;
            for (int o = 16; o > 0; o >>= 1) p += __shfl_down_sync(0xFFFFFFFFu, p, o);
            if (lane == 0) s_red[wp] = p;
            __syncthreads();
            if (t == 0) {
                float dot = s_red[0] + s_red[1] + s_red[2] + s_red[3]
                          + s_red[4] + s_red[5] + s_red[6] + s_red[7];
                float sc = dot - g_whalf[k];
                if (sc > ebv || (sc == ebv && k < ebi)) { ebv = sc; ebi = k; }
            }
            __syncthreads();
        }
        if (t == 0) {
            s_ind = ebi;
            atomicAdd(&g_loss, g_znorm[b] - 2.0f * ebv);
        }
    }
    __syncthreads();
    const int ind = s_ind;

    // ---- gather: out[b] = w[ind] (w row L2-hot) ----
    const float4* wr = (const float4*)(w + (size_t)ind * C_DIM);
    float4* o4 = (float4*)(out + (size_t)b * C_DIM);
#pragma unroll
    for (int cc = 0; cc < 2; cc++) {
        float4 wv = __ldg(&wr[t + cc * 256]);
        asm volatile("st.global.cs.v4.f32 [%0], {%1,%2,%3,%4};"
            :: "l"(o4 + t + cc * 256), "f"(wv.x), "f"(wv.y), "f"(wv.z), "f"(wv.w));
    }
}

__global__ void fin_k(float* out, int loss_idx, float inv_n) {
    out[loss_idx] = 12.5f * g_loss * inv_n;   // KLD_SCALE*(1+COMMITMENT_COST)*mse
}

extern "C" void kernel_launch(void* const* d_in, const int* in_sizes, int n_in,
                              void* d_out, int out_size)
{
    const float* z = (const float*)d_in[0];
    const float* w = (const float*)d_in[1];
    float* out = (float*)d_out;
    const int B = in_sizes[0] / C_DIM;   // 8192

    void* p_zb; cudaGetSymbolAddress(&p_zb, g_zb);
    void* p_wb; cudaGetSymbolAddress(&p_wb, g_wb);
    void* p_sc; cudaGetSymbolAddress(&p_sc, g_scores);

    cudaFuncSetAttribute(gemm_k, cudaFuncAttributeMaxDynamicSharedMemorySize, GSMEM);

    prep_k<<<K_DIM + B, 256>>>(z, w, (signed char*)p_zb, (signed char*)p_wb);

    dim3 ggrid(B / BM, K_DIM / BN);
    gemm_k<<<ggrid, 256, GSMEM>>>((const signed char*)p_zb,
                                  (const signed char*)p_wb,
                                  (__half*)p_sc);

    scanref_k<<<B, 256>>>(z, w, out);
    fin_k<<<1, 1>>>(out, out_size - 1, 1.0f / ((float)B * (float)C_DIM));
}